// round 1
// baseline (speedup 1.0000x reference)
#include <cuda_runtime.h>

#define BATCH 8
#define SEQL 2048
#define DIM 128
#define NROWS (BATCH * SEQL)
#define TS 64
#define TT 32
#define SCALE 0.08838834764831843f   // 1/sqrt(128)

typedef unsigned long long ull;

// Scratch (device globals: no allocations allowed)
__device__ __align__(16) float g_a[NROWS];
__device__ __align__(16) float g_k[NROWS];
__device__ float g_kmax[BATCH];
__device__ float g_kmin[BATCH];

// ---------------------------------------------------------------------------
// Kernel 1: per-row dot products.  a[r] = (x_r . rsum)/sqrt(d), k[r] = x_r . ent
// One warp per row; lane handles 4 contiguous elements (float4), shfl reduce.
// ---------------------------------------------------------------------------
__global__ void __launch_bounds__(256) rowdot_kernel(const float* __restrict__ X,
                                                     const float* __restrict__ rot,
                                                     const float* __restrict__ ent) {
    int lane = threadIdx.x & 31;
    int row = (blockIdx.x * blockDim.x + threadIdx.x) >> 5;
    if (row >= NROWS) return;

    float4 x = ((const float4*)X)[row * (DIM / 4) + lane];
    float4 e = ((const float4*)ent)[lane];
    const float* rp = rot + lane * 12;   // rot is [d,3] row-major; 4 d's = 12 floats
    float r0 = rp[0] + rp[1] + rp[2];
    float r1 = rp[3] + rp[4] + rp[5];
    float r2 = rp[6] + rp[7] + rp[8];
    float r3 = rp[9] + rp[10] + rp[11];

    float da = x.x * r0 + x.y * r1 + x.z * r2 + x.w * r3;
    float dk = x.x * e.x + x.y * e.y + x.z * e.z + x.w * e.w;

    #pragma unroll
    for (int o = 16; o > 0; o >>= 1) {
        da += __shfl_xor_sync(0xffffffffu, da, o);
        dk += __shfl_xor_sync(0xffffffffu, dk, o);
    }
    if (lane == 0) {
        g_a[row] = da * SCALE;
        g_k[row] = dk;
    }
}

// ---------------------------------------------------------------------------
// Kernel 2: per-batch min/max of k (for exact softmax row-max: rank-1 logits).
// ---------------------------------------------------------------------------
__global__ void __launch_bounds__(256) kminmax_kernel() {
    __shared__ float smx[256];
    __shared__ float smn[256];
    int b = blockIdx.x;
    int tid = threadIdx.x;
    float mx = -3.4e38f, mn = 3.4e38f;
    for (int i = tid; i < SEQL; i += 256) {
        float v = g_k[b * SEQL + i];
        mx = fmaxf(mx, v);
        mn = fminf(mn, v);
    }
    smx[tid] = mx; smn[tid] = mn;
    __syncthreads();
    for (int s = 128; s > 0; s >>= 1) {
        if (tid < s) {
            smx[tid] = fmaxf(smx[tid], smx[tid + s]);
            smn[tid] = fminf(smn[tid], smn[tid + s]);
        }
        __syncthreads();
    }
    if (tid == 0) { g_kmax[b] = smx[0]; g_kmin[b] = smn[0]; }
}

// ---------------------------------------------------------------------------
// Kernel 3: fused  O[b, s0:s0+64, :] = (exp(a ⊗ k - m) @ X_b) / Z
// 256 threads, 2 CTAs/SM. Smem-staged W tile (exp computed once per (s,t)),
// register-blocked 4s x 8d per thread with packed f32x2 FMA.
// ---------------------------------------------------------------------------
__device__ __forceinline__ ull splat2(float v) {
    ull r;
    asm("mov.b64 %0, {%1, %1};" : "=l"(r) : "f"(v));
    return r;
}
__device__ __forceinline__ void ffma2(ull& d, ull a, ull b) {
    asm("fma.rn.f32x2 %0, %1, %2, %0;" : "+l"(d) : "l"(a), "l"(b));
}

__global__ void __launch_bounds__(256, 2) attn_kernel(const float* __restrict__ X,
                                                      float* __restrict__ Out) {
    __shared__ __align__(16) float xs[TT][DIM];   // 16 KB: X chunk [t][d]
    __shared__ __align__(16) float ws[TT][TS];    //  8 KB: W chunk [t][s]
    __shared__ float zs[4][TS];                   // per-octet partial row sums

    int b = blockIdx.y;
    int s0 = blockIdx.x * TS;
    int tid = threadIdx.x;

    // --- W-phase identity: thread owns row s=sw, t-octet toct (8 t's per chunk)
    int sw = tid & 63;
    int toct = tid >> 6;                          // 0..3
    float a_r = g_a[b * SEQL + s0 + sw];
    float m_r = (a_r >= 0.f) ? a_r * g_kmax[b] : a_r * g_kmin[b];
    float zacc = 0.f;

    // --- GEMM identity: thread tile = 4 s-rows x 8 d-cols (two float4 halves)
    int sig = tid >> 4;                           // 0..15 -> s rows sig*4..+3
    int dj = tid & 15;                            // 0..15 -> d cols dj*4 and 64+dj*4

    ull acc[4][4];
    #pragma unroll
    for (int i = 0; i < 4; i++)
        #pragma unroll
        for (int j = 0; j < 4; j++) acc[i][j] = 0ull;

    const float4* Xb4 = (const float4*)(X + (size_t)b * SEQL * DIM);
    const float* kb = g_k + b * SEQL;

    // Prefetch chunk 0
    float4 xp[4], kp[2];
    {
        #pragma unroll
        for (int i = 0; i < 4; i++) xp[i] = Xb4[tid + i * 256];
        kp[0] = *(const float4*)&kb[toct * 8];
        kp[1] = *(const float4*)&kb[toct * 8 + 4];
    }

    for (int c = 0; c < SEQL / TT; ++c) {
        __syncthreads();  // previous chunk's GEMM readers done

        // Stage X chunk (prefetched in registers) into smem
        #pragma unroll
        for (int i = 0; i < 4; i++) ((float4*)xs)[tid + i * 256] = xp[i];

        // Compute W tile: w[s,t] = exp(a_s * k_t - m_s); accumulate Z partials
        float kv[8] = {kp[0].x, kp[0].y, kp[0].z, kp[0].w,
                       kp[1].x, kp[1].y, kp[1].z, kp[1].w};
        #pragma unroll
        for (int j = 0; j < 8; j++) {
            float w = __expf(fmaf(a_r, kv[j], -m_r));
            ws[toct * 8 + j][sw] = w;
            zacc += w;
        }
        __syncthreads();

        // Prefetch next chunk (LDG latency hidden under GEMM below)
        if (c + 1 < SEQL / TT) {
            const float4* p = Xb4 + (c + 1) * TT * (DIM / 4);
            #pragma unroll
            for (int i = 0; i < 4; i++) xp[i] = p[tid + i * 256];
            int t0 = (c + 1) * TT;
            kp[0] = *(const float4*)&kb[t0 + toct * 8];
            kp[1] = *(const float4*)&kb[t0 + toct * 8 + 4];
        }

        // GEMM: acc[4s][8d] += w[s,t] * x[t,d] over 32 t, packed f32x2 FMA
        #pragma unroll
        for (int t = 0; t < TT; ++t) {
            float4 wv = *(const float4*)&ws[t][sig * 4];
            float4 xa = *(const float4*)&xs[t][dj * 4];
            float4 xb = *(const float4*)&xs[t][64 + dj * 4];
            ull* pa = (ull*)&xa;
            ull* pb = (ull*)&xb;
            ull w0 = splat2(wv.x), w1 = splat2(wv.y);
            ull w2 = splat2(wv.z), w3 = splat2(wv.w);
            ffma2(acc[0][0], w0, pa[0]); ffma2(acc[0][1], w0, pa[1]);
            ffma2(acc[0][2], w0, pb[0]); ffma2(acc[0][3], w0, pb[1]);
            ffma2(acc[1][0], w1, pa[0]); ffma2(acc[1][1], w1, pa[1]);
            ffma2(acc[1][2], w1, pb[0]); ffma2(acc[1][3], w1, pb[1]);
            ffma2(acc[2][0], w2, pa[0]); ffma2(acc[2][1], w2, pa[1]);
            ffma2(acc[2][2], w2, pb[0]); ffma2(acc[2][3], w2, pb[1]);
            ffma2(acc[3][0], w3, pa[0]); ffma2(acc[3][1], w3, pa[1]);
            ffma2(acc[3][2], w3, pb[0]); ffma2(acc[3][3], w3, pb[1]);
        }
    }

    // Reduce Z partials (4 t-octets per s-row)
    zs[toct][sw] = zacc;
    __syncthreads();

    // Epilogue: divide by Z, vectorized stores
    #pragma unroll
    for (int i = 0; i < 4; i++) {
        int s = sig * 4 + i;
        float z = zs[0][s] + zs[1][s] + zs[2][s] + zs[3][s];
        float inv = 1.0f / z;
        float2 p0 = *(float2*)&acc[i][0];
        float2 p1 = *(float2*)&acc[i][1];
        float2 p2 = *(float2*)&acc[i][2];
        float2 p3 = *(float2*)&acc[i][3];
        float4 o0 = make_float4(p0.x * inv, p0.y * inv, p1.x * inv, p1.y * inv);
        float4 o1 = make_float4(p2.x * inv, p2.y * inv, p3.x * inv, p3.y * inv);
        float* orow = Out + ((size_t)b * SEQL + s0 + s) * DIM;
        *(float4*)&orow[dj * 4] = o0;
        *(float4*)&orow[64 + dj * 4] = o1;
    }
}

// ---------------------------------------------------------------------------
// Harness entry
// ---------------------------------------------------------------------------
extern "C" void kernel_launch(void* const* d_in, const int* in_sizes, int n_in,
                              void* d_out, int out_size) {
    const float* X = (const float*)d_in[0];    // [8, 2048, 128] f32
    const float* rot = (const float*)d_in[1];  // [384] f32
    const float* ent = (const float*)d_in[2];  // [128] f32
    float* Out = (float*)d_out;                // [8, 2048, 128] f32

    rowdot_kernel<<<NROWS / 8, 256>>>(X, rot, ent);
    kminmax_kernel<<<BATCH, 256>>>();
    attn_kernel<<<dim3(SEQL / TS, BATCH), 256>>>(X, Out);
}

// round 3
// speedup vs baseline: 3.0186x; 3.0186x over previous
#include <cuda_runtime.h>
#include <cuda_fp16.h>
#include <cstdint>

#define BATCH 8
#define SEQL 2048
#define DIM 128
#define NROWS (BATCH*SEQL)
#define SCALE 0.08838834764831843f    // 1/sqrt(128)
#define LOG2E 1.4426950408889634f
#define KT 32
#define NCHUNK (SEQL/KT)
#define WS 40     // W smem row stride (halves): 80B -> conflict-free ldmatrix
#define XS 136    // X smem row stride (halves): 272B -> conflict-free ldmatrix

__device__ __align__(16) float g_a2[NROWS];   // a * SCALE * log2(e)
__device__ __align__(16) float g_k[NROWS];
__device__ float g_kmax[BATCH];
__device__ float g_kmin[BATCH];
__device__ __align__(16) __half g_xh[(size_t)NROWS * DIM];   // X in fp16

// ---------------------------------------------------------------------------
// helpers
// ---------------------------------------------------------------------------
__device__ __forceinline__ uint32_t smem_u32(const void* p) {
    uint32_t a;
    asm("{ .reg .u64 t; cvta.to.shared.u64 t, %1; cvt.u32.u64 %0, t; }" : "=r"(a) : "l"(p));
    return a;
}
__device__ __forceinline__ float ex2f(float x) {
    float r; asm("ex2.approx.f32 %0, %1;" : "=f"(r) : "f"(x)); return r;
}
__device__ __forceinline__ uint32_t packh2(float a, float b) {
    __half2 h = __floats2half2_rn(a, b);
    return *(uint32_t*)&h;
}
__device__ __forceinline__ void ldsm4(uint32_t* r, uint32_t addr) {
    asm volatile("ldmatrix.sync.aligned.m8n8.x4.shared.b16 {%0,%1,%2,%3}, [%4];"
                 : "=r"(r[0]), "=r"(r[1]), "=r"(r[2]), "=r"(r[3]) : "r"(addr));
}
__device__ __forceinline__ void ldsm4t(uint32_t* r, uint32_t addr) {
    asm volatile("ldmatrix.sync.aligned.m8n8.x4.trans.shared.b16 {%0,%1,%2,%3}, [%4];"
                 : "=r"(r[0]), "=r"(r[1]), "=r"(r[2]), "=r"(r[3]) : "r"(addr));
}
__device__ __forceinline__ void mma16816(float* d, const uint32_t* a, const uint32_t* b) {
    asm volatile(
        "mma.sync.aligned.m16n8k16.row.col.f32.f16.f16.f32 "
        "{%0,%1,%2,%3}, {%4,%5,%6,%7}, {%8,%9}, {%0,%1,%2,%3};"
        : "+f"(d[0]), "+f"(d[1]), "+f"(d[2]), "+f"(d[3])
        : "r"(a[0]), "r"(a[1]), "r"(a[2]), "r"(a[3]), "r"(b[0]), "r"(b[1]));
}

// ---------------------------------------------------------------------------
// Kernel 1: per-row dots + X -> fp16 conversion (fused; X read once)
// ---------------------------------------------------------------------------
__global__ void __launch_bounds__(256) rowdot_kernel(const float* __restrict__ X,
                                                     const float* __restrict__ rot,
                                                     const float* __restrict__ ent) {
    int lane = threadIdx.x & 31;
    int row = (blockIdx.x * blockDim.x + threadIdx.x) >> 5;
    if (row >= NROWS) return;

    float4 x = ((const float4*)X)[(size_t)row * 32 + lane];

    // fp16 copy of X (for MMA B/operand data)
    uint2 v;
    v.x = packh2(x.x, x.y);
    v.y = packh2(x.z, x.w);
    *(uint2*)(g_xh + (size_t)row * DIM + lane * 4) = v;

    float4 e = ((const float4*)ent)[lane];
    const float* rp = rot + lane * 12;
    float r0 = rp[0] + rp[1] + rp[2];
    float r1 = rp[3] + rp[4] + rp[5];
    float r2 = rp[6] + rp[7] + rp[8];
    float r3 = rp[9] + rp[10] + rp[11];

    float da = x.x * r0 + x.y * r1 + x.z * r2 + x.w * r3;
    float dk = x.x * e.x + x.y * e.y + x.z * e.z + x.w * e.w;

    #pragma unroll
    for (int o = 16; o > 0; o >>= 1) {
        da += __shfl_xor_sync(0xffffffffu, da, o);
        dk += __shfl_xor_sync(0xffffffffu, dk, o);
    }
    if (lane == 0) {
        g_a2[row] = da * (SCALE * LOG2E);
        g_k[row] = dk;
    }
}

// ---------------------------------------------------------------------------
// Kernel 2: per-batch min/max of k (rank-1 logits -> exact row max)
// ---------------------------------------------------------------------------
__global__ void __launch_bounds__(256) kminmax_kernel() {
    __shared__ float smx[256];
    __shared__ float smn[256];
    int b = blockIdx.x;
    int tid = threadIdx.x;
    float mx = -3.4e38f, mn = 3.4e38f;
    for (int i = tid; i < SEQL; i += 256) {
        float v = g_k[b * SEQL + i];
        mx = fmaxf(mx, v);
        mn = fminf(mn, v);
    }
    smx[tid] = mx; smn[tid] = mn;
    __syncthreads();
    for (int s = 128; s > 0; s >>= 1) {
        if (tid < s) {
            smx[tid] = fmaxf(smx[tid], smx[tid + s]);
            smn[tid] = fminf(smn[tid], smn[tid + s]);
        }
        __syncthreads();
    }
    if (tid == 0) { g_kmax[b] = smx[0]; g_kmin[b] = smn[0]; }
}

// ---------------------------------------------------------------------------
// Kernel 3: fp16 mma.sync attention GEMM.
// Per CTA: D[128 s, 128 d] = softmax-weights(128 x 2048) @ X_b[2048, 128]
// W generated on the fly via ex2; double-buffered KT=32 chunks, 1 sync/chunk.
// ---------------------------------------------------------------------------
__global__ void __launch_bounds__(256, 1) attn_mma_kernel(float* __restrict__ Out) {
    __shared__ __half Wb[2][128 * WS];    // 20 KB
    __shared__ __half Xb[2][KT * XS];     // 17 KB
    __shared__ float zs[2][128];

    const int tid = threadIdx.x;
    const int wid = tid >> 5;
    const int lane = tid & 31;
    const int b = blockIdx.y;
    const int s0 = blockIdx.x * 128;

    // W-gen identity: row sw, t-half
    const int sw = tid & 127;
    const int thalf = tid >> 7;
    const int t0g = thalf * 16;
    const float a2 = g_a2[b * SEQL + s0 + sw];
    const float nm2 = -((a2 >= 0.f) ? a2 * g_kmax[b] : a2 * g_kmin[b]);
    float zacc = 0.f;
    const float* kb = g_k + b * SEQL;

    // X-stage identity: row xt, 16-wide d segment
    const int xt = tid & 31;
    const int xd0 = (tid >> 5) * 16;
    const __half* XHb = g_xh + (size_t)b * SEQL * DIM;

    // MMA identity: warp tile 32s x 64d; SMSP pairs get opposite phase order
    const int m0 = (wid & 3) * 32;
    const int n0 = (wid >> 2) * 64;
    const int swapord = (wid >> 2) & 1;

    float acc[2][8][4];
    #pragma unroll
    for (int i = 0; i < 2; i++)
        #pragma unroll
        for (int j = 0; j < 8; j++)
            #pragma unroll
            for (int q = 0; q < 4; q++) acc[i][j][q] = 0.f;

    // ---- staging helpers (inline lambdas) ----
    auto ldX = [&](uint4& p0, uint4& p1, int c) {
        const uint4* p = (const uint4*)(XHb + (size_t)(c * KT + xt) * DIM + xd0);
        p0 = p[0]; p1 = p[1];
    };
    auto stageAll = [&](int c, int buf, const uint4& p0, const uint4& p1) {
        // X chunk (already fp16)
        *(uint4*)&Xb[buf][xt * XS + xd0] = p0;
        *(uint4*)&Xb[buf][xt * XS + xd0 + 8] = p1;
        // W chunk: 16 exps for (row sw, t = c*KT + t0g + 0..15)
        const float4* kc = (const float4*)(kb + c * KT + t0g);
        float4 k0 = kc[0], k1 = kc[1], k2 = kc[2], k3 = kc[3];
        float w0 = ex2f(fmaf(a2, k0.x, nm2)), w1 = ex2f(fmaf(a2, k0.y, nm2));
        float w2 = ex2f(fmaf(a2, k0.z, nm2)), w3 = ex2f(fmaf(a2, k0.w, nm2));
        float w4 = ex2f(fmaf(a2, k1.x, nm2)), w5 = ex2f(fmaf(a2, k1.y, nm2));
        float w6 = ex2f(fmaf(a2, k1.z, nm2)), w7 = ex2f(fmaf(a2, k1.w, nm2));
        float w8 = ex2f(fmaf(a2, k2.x, nm2)), w9 = ex2f(fmaf(a2, k2.y, nm2));
        float wa = ex2f(fmaf(a2, k2.z, nm2)), wb_ = ex2f(fmaf(a2, k2.w, nm2));
        float wc = ex2f(fmaf(a2, k3.x, nm2)), wd = ex2f(fmaf(a2, k3.y, nm2));
        float we = ex2f(fmaf(a2, k3.z, nm2)), wf = ex2f(fmaf(a2, k3.w, nm2));
        zacc += ((w0 + w1) + (w2 + w3)) + ((w4 + w5) + (w6 + w7))
              + ((w8 + w9) + (wa + wb_)) + ((wc + wd) + (we + wf));
        uint4 q0, q1;
        q0.x = packh2(w0, w1); q0.y = packh2(w2, w3);
        q0.z = packh2(w4, w5); q0.w = packh2(w6, w7);
        q1.x = packh2(w8, w9); q1.y = packh2(wa, wb_);
        q1.z = packh2(wc, wd); q1.w = packh2(we, wf);
        __half* wr = &Wb[buf][sw * WS + t0g];
        *(uint4*)wr = q0;
        *(uint4*)(wr + 8) = q1;
    };
    auto mmaPhase = [&](int buf) {
        uint32_t wbB = smem_u32(&Wb[buf][0]);
        uint32_t xbB = smem_u32(&Xb[buf][0]);
        int lr = lane & 15, lc = lane >> 4;
        #pragma unroll
        for (int kp = 0; kp < 2; ++kp) {
            uint32_t af[2][4];
            #pragma unroll
            for (int mt = 0; mt < 2; ++mt)
                ldsm4(af[mt], wbB + (uint32_t)(((m0 + mt * 16 + lr) * WS + kp * 16 + lc * 8) * 2));
            uint32_t bf[4][4];
            #pragma unroll
            for (int q = 0; q < 4; ++q)
                ldsm4t(bf[q], xbB + (uint32_t)(((kp * 16 + lr) * XS + n0 + q * 16 + lc * 8) * 2));
            #pragma unroll
            for (int mt = 0; mt < 2; ++mt)
                #pragma unroll
                for (int nt = 0; nt < 8; ++nt)
                    mma16816(acc[mt][nt], af[mt], &bf[nt >> 1][(nt & 1) * 2]);
        }
    };

    // ---- prologue: stage chunk 0, prefetch chunks 1 & 2 ----
    uint4 pa0, pa1, pb0, pb1;
    ldX(pa0, pa1, 0);
    stageAll(0, 0, pa0, pa1);
    ldX(pa0, pa1, 1);
    ldX(pb0, pb1, 2);
    __syncthreads();

    // ---- main loop: 1 sync per chunk; stage(c+1) and mma(c) share a region ----
    for (int c = 0; c < NCHUNK; c += 2) {
        // region c: mma on buf0, stage chunk c+1 -> buf1 (regs A)
        if (swapord) { mmaPhase(0); stageAll(c + 1, 1, pa0, pa1); }
        else         { stageAll(c + 1, 1, pa0, pa1); mmaPhase(0); }
        { int nc = c + 3 < NCHUNK ? c + 3 : NCHUNK - 1; ldX(pa0, pa1, nc); }
        __syncthreads();
        // region c+1: mma on buf1, stage chunk c+2 -> buf0 (regs B)
        if (swapord) { mmaPhase(1); if (c + 2 < NCHUNK) stageAll(c + 2, 0, pb0, pb1); }
        else         { if (c + 2 < NCHUNK) stageAll(c + 2, 0, pb0, pb1); mmaPhase(1); }
        { int nc = c + 4 < NCHUNK ? c + 4 : NCHUNK - 1; ldX(pb0, pb1, nc); }
        __syncthreads();
    }

    // ---- Z reduce ----
    zs[thalf][sw] = zacc;
    __syncthreads();

    // ---- epilogue: scale by 1/Z and store ----
    const int lr4 = lane >> 2;
    const int lc2 = (lane & 3) * 2;
    #pragma unroll
    for (int mt = 0; mt < 2; ++mt) {
        int r0 = m0 + mt * 16 + lr4;
        float i0 = 1.0f / (zs[0][r0] + zs[1][r0]);
        float i1 = 1.0f / (zs[0][r0 + 8] + zs[1][r0 + 8]);
        float* o0 = Out + ((size_t)b * SEQL + s0 + r0) * DIM + n0 + lc2;
        float* o1 = o0 + 8 * DIM;
        #pragma unroll
        for (int nt = 0; nt < 8; ++nt) {
            float2 v0 = make_float2(acc[mt][nt][0] * i0, acc[mt][nt][1] * i0);
            float2 v1 = make_float2(acc[mt][nt][2] * i1, acc[mt][nt][3] * i1);
            *(float2*)(o0 + nt * 8) = v0;
            *(float2*)(o1 + nt * 8) = v1;
        }
    }
}

// ---------------------------------------------------------------------------
// Harness entry
// ---------------------------------------------------------------------------
extern "C" void kernel_launch(void* const* d_in, const int* in_sizes, int n_in,
                              void* d_out, int out_size) {
    const float* X = (const float*)d_in[0];    // [8, 2048, 128] f32
    const float* rot = (const float*)d_in[1];  // [384] f32
    const float* ent = (const float*)d_in[2];  // [128] f32
    float* Out = (float*)d_out;                // [8, 2048, 128] f32

    rowdot_kernel<<<NROWS / 8, 256>>>(X, rot, ent);
    kminmax_kernel<<<BATCH, 256>>>();
    attn_mma_kernel<<<dim3(SEQL / 128, BATCH), 256>>>(Out);
}

// round 5
// speedup vs baseline: 3.4957x; 1.1581x over previous
#include <cuda_runtime.h>
#include <cuda_fp16.h>
#include <cstdint>

#define BATCH 8
#define SEQL 2048
#define DIM 128
#define NROWS (BATCH*SEQL)
#define SCALE 0.08838834764831843f    // 1/sqrt(128)
#define LOG2E 1.4426950408889634f
#define KT 32
#define NCHUNK (SEQL/KT)
#define WS 40     // W smem row stride (halves): 80B -> conflict-free ldmatrix
#define XS 136    // X smem row stride (halves): 272B -> conflict-free ldmatrix

__device__ __align__(16) float g_a2[NROWS];   // a * SCALE * log2(e)
__device__ __align__(16) float g_k[NROWS];
__device__ float g_kmax[BATCH];
__device__ float g_kmin[BATCH];
__device__ __align__(16) __half g_xh[(size_t)NROWS * DIM];   // X in fp16

// ---------------------------------------------------------------------------
// helpers
// ---------------------------------------------------------------------------
__device__ __forceinline__ uint32_t smem_u32(const void* p) {
    uint32_t a;
    asm("{ .reg .u64 t; cvta.to.shared.u64 t, %1; cvt.u32.u64 %0, t; }" : "=r"(a) : "l"(p));
    return a;
}
__device__ __forceinline__ float ex2f(float x) {
    float r; asm("ex2.approx.f32 %0, %1;" : "=f"(r) : "f"(x)); return r;
}
// packs lo=b, hi=a  (PTX cvt.rn.f16x2.f32 d, a, b -> a in upper half)
__device__ __forceinline__ uint32_t packh2f(float hi, float lo) {
    uint32_t r;
    asm("cvt.rn.f16x2.f32 %0, %1, %2;" : "=r"(r) : "f"(hi), "f"(lo));
    return r;
}
__device__ __forceinline__ void ldsm4(uint32_t* r, uint32_t addr) {
    asm volatile("ldmatrix.sync.aligned.m8n8.x4.shared.b16 {%0,%1,%2,%3}, [%4];"
                 : "=r"(r[0]), "=r"(r[1]), "=r"(r[2]), "=r"(r[3]) : "r"(addr));
}
__device__ __forceinline__ void ldsm4t(uint32_t* r, uint32_t addr) {
    asm volatile("ldmatrix.sync.aligned.m8n8.x4.trans.shared.b16 {%0,%1,%2,%3}, [%4];"
                 : "=r"(r[0]), "=r"(r[1]), "=r"(r[2]), "=r"(r[3]) : "r"(addr));
}
__device__ __forceinline__ void mma16816(float* d, const uint32_t* a, const uint32_t* b) {
    asm volatile(
        "mma.sync.aligned.m16n8k16.row.col.f32.f16.f16.f32 "
        "{%0,%1,%2,%3}, {%4,%5,%6,%7}, {%8,%9}, {%0,%1,%2,%3};"
        : "+f"(d[0]), "+f"(d[1]), "+f"(d[2]), "+f"(d[3])
        : "r"(a[0]), "r"(a[1]), "r"(a[2]), "r"(a[3]), "r"(b[0]), "r"(b[1]));
}

// ---------------------------------------------------------------------------
// Kernel 1: per-row dots + X -> fp16.
// Warp covers 4 rows; each lane loads 4 float4s from its row (cols c8+8j)
// -> 4 coalesced LDG.128 per thread (MLP=4), full 128-column coverage.
// ---------------------------------------------------------------------------
__global__ void __launch_bounds__(256) rowdot_kernel(const float* __restrict__ X,
                                                     const float* __restrict__ rot,
                                                     const float* __restrict__ ent) {
    __shared__ float rs[DIM];
    const int tid = threadIdx.x;
    if (tid < DIM) {
        const float* rp = rot + tid * 3;
        rs[tid] = rp[0] + rp[1] + rp[2];
    }
    __syncthreads();

    const int lane = tid & 31;
    const int wid = tid >> 5;
    const int c8 = lane & 7;          // float4 chunk id base (cols c8+8j)
    const int rg = lane >> 3;         // row within warp group 0..3
    const int row = blockIdx.x * 32 + wid * 4 + rg;

    const float4* Xr = (const float4*)X + (size_t)row * 32;

    float4 x[4];
    #pragma unroll
    for (int j = 0; j < 4; ++j) x[j] = Xr[c8 + 8 * j];

    float da = 0.f, dk = 0.f;
    #pragma unroll
    for (int j = 0; j < 4; ++j) {
        const int c = (c8 + 8 * j) * 4;
        // fp16 copy
        uint2 v;
        v.x = packh2f(x[j].y, x[j].x);
        v.y = packh2f(x[j].w, x[j].z);
        *(uint2*)(g_xh + (size_t)row * DIM + c) = v;

        da += x[j].x * rs[c] + x[j].y * rs[c + 1] + x[j].z * rs[c + 2] + x[j].w * rs[c + 3];
        dk += x[j].x * ent[c] + x[j].y * ent[c + 1] + x[j].z * ent[c + 2] + x[j].w * ent[c + 3];
    }

    da += __shfl_xor_sync(~0u, da, 4); dk += __shfl_xor_sync(~0u, dk, 4);
    da += __shfl_xor_sync(~0u, da, 2); dk += __shfl_xor_sync(~0u, dk, 2);
    da += __shfl_xor_sync(~0u, da, 1); dk += __shfl_xor_sync(~0u, dk, 1);

    if (c8 == 0) {
        g_a2[row] = da * (SCALE * LOG2E);
        g_k[row] = dk;
    }
}

// ---------------------------------------------------------------------------
// Kernel 2: per-batch min/max of k (rank-1 logits -> exact row max)
// ---------------------------------------------------------------------------
__global__ void __launch_bounds__(256) kminmax_kernel() {
    __shared__ float smx[256];
    __shared__ float smn[256];
    int b = blockIdx.x;
    int tid = threadIdx.x;
    float mx = -3.4e38f, mn = 3.4e38f;
    for (int i = tid; i < SEQL; i += 256) {
        float v = g_k[b * SEQL + i];
        mx = fmaxf(mx, v);
        mn = fminf(mn, v);
    }
    smx[tid] = mx; smn[tid] = mn;
    __syncthreads();
    for (int s = 128; s > 0; s >>= 1) {
        if (tid < s) {
            smx[tid] = fmaxf(smx[tid], smx[tid + s]);
            smn[tid] = fminf(smn[tid], smn[tid + s]);
        }
        __syncthreads();
    }
    if (tid == 0) { g_kmax[b] = smx[0]; g_kmin[b] = smn[0]; }
}

// ---------------------------------------------------------------------------
// Kernel 3: fp16 mma.sync attention GEMM, 512 threads (16 warps, 4/SMSP).
// Per CTA: D[128 s, 128 d] = softmax-weights(128 x 2048) @ X_b[2048, 128].
// Z accumulated on the tensor pipe via an all-ones B fragment (warp col 0).
// ---------------------------------------------------------------------------
__global__ void __launch_bounds__(512, 1) attn_mma_kernel(float* __restrict__ Out) {
    __shared__ __half Wb[2][128 * WS];    // 20 KB
    __shared__ __half Xb[2][KT * XS];     // 17 KB
    __shared__ float zs[128];

    const int tid = threadIdx.x;
    const int wid = tid >> 5;
    const int lane = tid & 31;
    const int b = blockIdx.y;
    const int s0 = blockIdx.x * 128;

    // W-gen identity: row sw, t-offset tq*8 (8 exps per thread per chunk)
    const int sw = tid & 127;
    const int tq = tid >> 7;              // 0..3
    const float a2 = g_a2[b * SEQL + s0 + sw];
    const float nm2 = -((a2 >= 0.f) ? a2 * g_kmax[b] : a2 * g_kmin[b]);
    const float* kb = g_k + b * SEQL;

    // X-stage identity: row xt, 8-wide d segment
    const int xt = tid >> 4;              // 0..31
    const int xd0 = (tid & 15) * 8;
    const __half* XHb = g_xh + (size_t)b * SEQL * DIM;

    // MMA identity: 4x4 warp grid, warp tile 32s x 32d
    const int m0 = (wid & 3) * 32;
    const int n0 = (wid >> 2) * 32;
    const bool zwarp = (wid >> 2) == 0;   // warp column 0 also accumulates Z
    const uint32_t onesb[2] = {0x3C003C00u, 0x3C003C00u};

    float acc[2][4][4];
    float accz[2][4];
    #pragma unroll
    for (int i = 0; i < 2; i++) {
        #pragma unroll
        for (int q = 0; q < 4; q++) accz[i][q] = 0.f;
        #pragma unroll
        for (int j = 0; j < 4; j++)
            #pragma unroll
            for (int q = 0; q < 4; q++) acc[i][j][q] = 0.f;
    }

    const uint32_t wbB0 = smem_u32(&Wb[0][0]), wbB1 = smem_u32(&Wb[1][0]);
    const uint32_t xbB0 = smem_u32(&Xb[0][0]), xbB1 = smem_u32(&Xb[1][0]);

    auto ldX = [&](uint4& p, int c) {
        p = *(const uint4*)(XHb + (size_t)(c * KT + xt) * DIM + xd0);
    };
    auto stageX = [&](int buf, const uint4& p) {
        *(uint4*)&Xb[buf][xt * XS + xd0] = p;
    };
    auto stageW = [&](int c, int buf) {
        const float4* kc = (const float4*)(kb + c * KT + tq * 8);
        float4 k0 = kc[0], k1 = kc[1];
        float w0 = ex2f(fmaf(a2, k0.x, nm2)), w1 = ex2f(fmaf(a2, k0.y, nm2));
        float w2 = ex2f(fmaf(a2, k0.z, nm2)), w3 = ex2f(fmaf(a2, k0.w, nm2));
        float w4 = ex2f(fmaf(a2, k1.x, nm2)), w5 = ex2f(fmaf(a2, k1.y, nm2));
        float w6 = ex2f(fmaf(a2, k1.z, nm2)), w7 = ex2f(fmaf(a2, k1.w, nm2));
        uint4 q;
        q.x = packh2f(w1, w0); q.y = packh2f(w3, w2);
        q.z = packh2f(w5, w4); q.w = packh2f(w7, w6);
        *(uint4*)&Wb[buf][sw * WS + tq * 8] = q;
    };
    auto mmaPhase = [&](int buf) {
        const uint32_t wbB = buf ? wbB1 : wbB0;
        const uint32_t xbB = buf ? xbB1 : xbB0;
        const int lr = lane & 15, lc = lane >> 4;
        #pragma unroll
        for (int kp = 0; kp < 2; ++kp) {
            uint32_t af[2][4];
            #pragma unroll
            for (int mt = 0; mt < 2; ++mt)
                ldsm4(af[mt], wbB + (uint32_t)(((m0 + mt * 16 + lr) * WS + kp * 16 + lc * 8) * 2));
            uint32_t bf[2][4];
            #pragma unroll
            for (int q = 0; q < 2; ++q)
                ldsm4t(bf[q], xbB + (uint32_t)(((kp * 16 + lr) * XS + n0 + q * 16 + lc * 8) * 2));
            #pragma unroll
            for (int mt = 0; mt < 2; ++mt) {
                #pragma unroll
                for (int nt = 0; nt < 4; ++nt)
                    mma16816(acc[mt][nt], af[mt], &bf[nt >> 1][(nt & 1) * 2]);
                if (zwarp) mma16816(accz[mt], af[mt], onesb);
            }
        }
    };

    // ---- prologue ----
    uint4 xp;
    ldX(xp, 0);
    stageX(0, xp);
    stageW(0, 0);
    ldX(xp, 1);
    __syncthreads();

    // ---- main loop: one sync per chunk; stage(c+1) overlaps mma(c) ----
    for (int c = 0; c < NCHUNK; ++c) {
        const int buf = c & 1;
        if (c + 1 < NCHUNK) { stageX(buf ^ 1, xp); stageW(c + 1, buf ^ 1); }
        if (c + 2 < NCHUNK) ldX(xp, c + 2);
        mmaPhase(buf);
        __syncthreads();
    }

    // ---- publish Z (warp column 0; identical values across the lane quad) ----
    if (zwarp && (lane & 3) == 0) {
        const int lr4 = lane >> 2;
        #pragma unroll
        for (int mt = 0; mt < 2; ++mt) {
            zs[m0 + mt * 16 + lr4] = accz[mt][0];
            zs[m0 + mt * 16 + lr4 + 8] = accz[mt][2];
        }
    }
    __syncthreads();

    // ---- epilogue: scale by 1/Z and store ----
    const int lr4 = lane >> 2;
    const int lc2 = (lane & 3) * 2;
    #pragma unroll
    for (int mt = 0; mt < 2; ++mt) {
        const int r0 = m0 + mt * 16 + lr4;
        const float i0 = 1.0f / zs[r0];
        const float i1 = 1.0f / zs[r0 + 8];
        float* o0 = Out + ((size_t)b * SEQL + s0 + r0) * DIM + n0 + lc2;
        float* o1 = o0 + 8 * DIM;
        #pragma unroll
        for (int nt = 0; nt < 4; ++nt) {
            *(float2*)(o0 + nt * 8) = make_float2(acc[mt][nt][0] * i0, acc[mt][nt][1] * i0);
            *(float2*)(o1 + nt * 8) = make_float2(acc[mt][nt][2] * i1, acc[mt][nt][3] * i1);
        }
    }
}

// ---------------------------------------------------------------------------
// Harness entry
// ---------------------------------------------------------------------------
extern "C" void kernel_launch(void* const* d_in, const int* in_sizes, int n_in,
                              void* d_out, int out_size) {
    const float* X = (const float*)d_in[0];    // [8, 2048, 128] f32
    const float* rot = (const float*)d_in[1];  // [384] f32
    const float* ent = (const float*)d_in[2];  // [128] f32
    float* Out = (float*)d_out;                // [8, 2048, 128] f32

    rowdot_kernel<<<NROWS / 32, 256>>>(X, rot, ent);
    kminmax_kernel<<<BATCH, 256>>>();
    attn_mma_kernel<<<dim3(SEQL / 128, BATCH), 512>>>(Out);
}

// round 10
// speedup vs baseline: 3.9051x; 1.1171x over previous
#include <cuda_runtime.h>
#include <cuda_fp16.h>
#include <cstdint>

#define BATCH 8
#define SEQL 2048
#define DIM 128
#define NROWS (BATCH*SEQL)
#define SCALE 0.08838834764831843f    // 1/sqrt(128)
#define LOG2E 1.4426950408889634f
#define KT 32
#define NCHUNK (SEQL/KT)
#define NBUF 2
#define WS 40     // W smem row stride (halves): 80B -> conflict-free ldmatrix
#define XS 136    // X smem row stride (halves): 272B -> conflict-free ldmatrix

typedef unsigned long long ull;

__device__ __align__(16) float g_a2[NROWS];   // a * SCALE * log2(e)
__device__ __align__(16) float g_k[NROWS];
__device__ unsigned g_kmaxu[BATCH];           // order-encoded max(k)   (zero-init ok)
__device__ unsigned g_knegu[BATCH];           // order-encoded max(-k)  (zero-init ok)
__device__ __align__(16) __half g_xh[(size_t)NROWS * DIM];   // X in fp16

// ---------------------------------------------------------------------------
// helpers
// ---------------------------------------------------------------------------
__device__ __forceinline__ uint32_t smem_u32(const void* p) {
    uint32_t a;
    asm("{ .reg .u64 t; cvta.to.shared.u64 t, %1; cvt.u32.u64 %0, t; }" : "=r"(a) : "l"(p));
    return a;
}
__device__ __forceinline__ float ex2f(float x) {
    float r; asm("ex2.approx.f32 %0, %1;" : "=f"(r) : "f"(x)); return r;
}
// packs lo=b, hi=a
__device__ __forceinline__ uint32_t packh2f(float hi, float lo) {
    uint32_t r;
    asm("cvt.rn.f16x2.f32 %0, %1, %2;" : "=r"(r) : "f"(hi), "f"(lo));
    return r;
}
// order-preserving float<->uint encode (monotonic; 0 below all real encodes)
__device__ __forceinline__ unsigned fenc(float x) {
    unsigned b = __float_as_uint(x);
    return (b & 0x80000000u) ? ~b : (b | 0x80000000u);
}
__device__ __forceinline__ float fdec(unsigned u) {
    return __uint_as_float((u & 0x80000000u) ? (u & 0x7FFFFFFFu) : ~u);
}
__device__ __forceinline__ void ldsm4(uint32_t* r, uint32_t addr) {
    asm volatile("ldmatrix.sync.aligned.m8n8.x4.shared.b16 {%0,%1,%2,%3}, [%4];"
                 : "=r"(r[0]), "=r"(r[1]), "=r"(r[2]), "=r"(r[3]) : "r"(addr));
}
__device__ __forceinline__ void ldsm4t(uint32_t* r, uint32_t addr) {
    asm volatile("ldmatrix.sync.aligned.m8n8.x4.trans.shared.b16 {%0,%1,%2,%3}, [%4];"
                 : "=r"(r[0]), "=r"(r[1]), "=r"(r[2]), "=r"(r[3]) : "r"(addr));
}
__device__ __forceinline__ void mma16816(float* d, const uint32_t* a, const uint32_t* b) {
    asm volatile(
        "mma.sync.aligned.m16n8k16.row.col.f32.f16.f16.f32 "
        "{%0,%1,%2,%3}, {%4,%5,%6,%7}, {%8,%9}, {%0,%1,%2,%3};"
        : "+f"(d[0]), "+f"(d[1]), "+f"(d[2]), "+f"(d[3])
        : "r"(a[0]), "r"(a[1]), "r"(a[2]), "r"(a[3]), "r"(b[0]), "r"(b[1]));
}
__device__ __forceinline__ void mbar_init(uint32_t a, uint32_t cnt) {
    asm volatile("mbarrier.init.shared.b64 [%0], %1;" :: "r"(a), "r"(cnt) : "memory");
}
__device__ __forceinline__ void mbar_arrive(uint32_t a) {
    asm volatile("mbarrier.arrive.shared.b64 _, [%0];" :: "r"(a) : "memory");
}
__device__ __forceinline__ void mbar_wait(uint32_t a, uint32_t par) {
    asm volatile(
        "{\n\t.reg .pred P;\n"
        "W%=:\n\t"
        "mbarrier.try_wait.parity.acquire.cta.shared::cta.b64 P, [%0], %1, 0x989680;\n\t"
        "@!P bra W%=;\n\t}"
        :: "r"(a), "r"(par) : "memory");
}

// ---------------------------------------------------------------------------
// Kernel 1: per-row dots + X -> fp16 + fused per-batch k min/max atomics.
// Warp covers 4 rows; each lane loads 4 float4s (cols c8+8j).
// ---------------------------------------------------------------------------
__global__ void __launch_bounds__(256) rowdot_kernel(const float* __restrict__ X,
                                                     const float* __restrict__ rot,
                                                     const float* __restrict__ ent) {
    __shared__ float rs[DIM];
    const int tid = threadIdx.x;
    if (tid < DIM) {
        const float* rp = rot + tid * 3;
        rs[tid] = rp[0] + rp[1] + rp[2];
    }
    __syncthreads();

    const int lane = tid & 31;
    const int wid = tid >> 5;
    const int c8 = lane & 7;
    const int rg = lane >> 3;
    const int row = blockIdx.x * 32 + wid * 4 + rg;

    const float4* Xr = (const float4*)X + (size_t)row * 32;

    float4 x[4];
    #pragma unroll
    for (int j = 0; j < 4; ++j) x[j] = Xr[c8 + 8 * j];

    float da = 0.f, dk = 0.f;
    #pragma unroll
    for (int j = 0; j < 4; ++j) {
        const int c = (c8 + 8 * j) * 4;
        uint2 v;
        v.x = packh2f(x[j].y, x[j].x);
        v.y = packh2f(x[j].w, x[j].z);
        *(uint2*)(g_xh + (size_t)row * DIM + c) = v;

        da += x[j].x * rs[c] + x[j].y * rs[c + 1] + x[j].z * rs[c + 2] + x[j].w * rs[c + 3];
        dk += x[j].x * ent[c] + x[j].y * ent[c + 1] + x[j].z * ent[c + 2] + x[j].w * ent[c + 3];
    }

    da += __shfl_xor_sync(~0u, da, 4); dk += __shfl_xor_sync(~0u, dk, 4);
    da += __shfl_xor_sync(~0u, da, 2); dk += __shfl_xor_sync(~0u, dk, 2);
    da += __shfl_xor_sync(~0u, da, 1); dk += __shfl_xor_sync(~0u, dk, 1);

    if (c8 == 0) {
        g_a2[row] = da * (SCALE * LOG2E);
        g_k[row] = dk;
    }
    // warp-level min/max over its 4 rows, one atomic pair per warp
    float kx = dk, kn = dk;
    kx = fmaxf(kx, __shfl_xor_sync(~0u, kx, 8));  kn = fminf(kn, __shfl_xor_sync(~0u, kn, 8));
    kx = fmaxf(kx, __shfl_xor_sync(~0u, kx, 16)); kn = fminf(kn, __shfl_xor_sync(~0u, kn, 16));
    if (lane == 0) {
        const int bt = row >> 11;
        atomicMax(&g_kmaxu[bt], fenc(kx));
        atomicMax(&g_knegu[bt], fenc(-kn));
    }
}

// ---------------------------------------------------------------------------
// Kernel 2: warp-specialized fp16 mma.sync attention GEMM.
// 640 threads = 16 consumer warps (4x4 grid, 32s x 32d tiles, ldsm+HMMA only)
//             +  4 producer warps (LDG + ex2 + pack + STS only), 1 each /SMSP.
// mbarrier full/empty ring (NBUF=2), no __syncthreads in the main loop.
// ---------------------------------------------------------------------------
__global__ void __launch_bounds__(640, 1) attn_mma_kernel(float* __restrict__ Out) {
    __shared__ __half Wb[NBUF][128 * WS];    // 20 KB
    __shared__ __half Xb[NBUF][KT * XS];     // 17 KB
    __shared__ float zs[128];
    __shared__ __align__(8) ull s_mbar[2 * NBUF];  // [0..1] full, [2..3] empty

    const int tid = threadIdx.x;
    const int wid = tid >> 5;
    const int lane = tid & 31;
    const int b = blockIdx.y;
    const int s0 = blockIdx.x * 128;
    const uint32_t mb = smem_u32((const void*)&s_mbar[0]);

    if (tid == 0) {
        #pragma unroll
        for (int s = 0; s < NBUF; ++s) {
            mbar_init(mb + 8 * s, 128);              // full: 128 producer arrivals
            mbar_init(mb + 8 * (NBUF + s), 512);     // empty: 512 consumer arrivals
        }
    }
    __syncthreads();

    if (wid >= 16) {
        // ============================ PRODUCER ============================
        const int ptid = tid - 512;                  // 0..127
        const float a2 = g_a2[b * SEQL + s0 + ptid];
        const float kmx = fdec(g_kmaxu[b]);
        const float kmn = -fdec(g_knegu[b]);
        const float nm2 = -((a2 >= 0.f) ? a2 * kmx : a2 * kmn);
        const float* kb = g_k + b * SEQL;
        const __half* XHb = g_xh + (size_t)b * SEQL * DIM;
        const int xtp = ptid >> 2;                   // 0..31  (X row)
        const int xdp = (ptid & 3) * 32;             // halves offset (32 halves)

        for (int c = 0; c < NCHUNK; ++c) {
            const int st = c & 1;
            if (c >= NBUF) mbar_wait(mb + 8 * (NBUF + st), ((c >> 1) - 1) & 1);

            // stage X: 32 halves = 4 x uint4
            const uint4* xsrc = (const uint4*)(XHb + (size_t)(c * KT + xtp) * DIM + xdp);
            uint4 v0 = xsrc[0], v1 = xsrc[1], v2 = xsrc[2], v3 = xsrc[3];
            uint4* xdst = (uint4*)&Xb[st][xtp * XS + xdp];
            xdst[0] = v0; xdst[1] = v1; xdst[2] = v2; xdst[3] = v3;

            // stage W row ptid: 32 exps -> 4 x uint4
            const float4* kc = (const float4*)(kb + c * KT);
            uint4* wdst = (uint4*)&Wb[st][ptid * WS];
            #pragma unroll
            for (int j = 0; j < 4; ++j) {
                float4 k0 = kc[2 * j], k1 = kc[2 * j + 1];
                float w0 = ex2f(fmaf(a2, k0.x, nm2)), w1 = ex2f(fmaf(a2, k0.y, nm2));
                float w2 = ex2f(fmaf(a2, k0.z, nm2)), w3 = ex2f(fmaf(a2, k0.w, nm2));
                float w4 = ex2f(fmaf(a2, k1.x, nm2)), w5 = ex2f(fmaf(a2, k1.y, nm2));
                float w6 = ex2f(fmaf(a2, k1.z, nm2)), w7 = ex2f(fmaf(a2, k1.w, nm2));
                uint4 q;
                q.x = packh2f(w1, w0); q.y = packh2f(w3, w2);
                q.z = packh2f(w5, w4); q.w = packh2f(w7, w6);
                wdst[j] = q;
            }
            mbar_arrive(mb + 8 * st);
        }
    } else {
        // ============================ CONSUMER ============================
        const int m0 = (wid & 3) * 32;
        const int n0 = (wid >> 2) * 32;
        const bool zwarp = (wid >> 2) == 0;
        const uint32_t onesb[2] = {0x3C003C00u, 0x3C003C00u};

        float acc[2][4][4];
        float accz[2][4];
        #pragma unroll
        for (int i = 0; i < 2; i++) {
            #pragma unroll
            for (int q = 0; q < 4; q++) accz[i][q] = 0.f;
            #pragma unroll
            for (int j = 0; j < 4; j++)
                #pragma unroll
                for (int q = 0; q < 4; q++) acc[i][j][q] = 0.f;
        }

        const uint32_t wbB0 = smem_u32(&Wb[0][0]), wbB1 = smem_u32(&Wb[1][0]);
        const uint32_t xbB0 = smem_u32(&Xb[0][0]), xbB1 = smem_u32(&Xb[1][0]);
        const int lr = lane & 15, lc = lane >> 4;

        for (int c = 0; c < NCHUNK; ++c) {
            const int st = c & 1;
            mbar_wait(mb + 8 * st, (c >> 1) & 1);

            const uint32_t wbB = st ? wbB1 : wbB0;
            const uint32_t xbB = st ? xbB1 : xbB0;
            #pragma unroll
            for (int kp = 0; kp < 2; ++kp) {
                uint32_t af[2][4];
                #pragma unroll
                for (int mt = 0; mt < 2; ++mt)
                    ldsm4(af[mt], wbB + (uint32_t)(((m0 + mt * 16 + lr) * WS + kp * 16 + lc * 8) * 2));
                uint32_t bf[2][4];
                #pragma unroll
                for (int q = 0; q < 2; ++q)
                    ldsm4t(bf[q], xbB + (uint32_t)(((kp * 16 + lr) * XS + n0 + q * 16 + lc * 8) * 2));
                #pragma unroll
                for (int mt = 0; mt < 2; ++mt) {
                    #pragma unroll
                    for (int nt = 0; nt < 4; ++nt)
                        mma16816(acc[mt][nt], af[mt], &bf[nt >> 1][(nt & 1) * 2]);
                    if (zwarp) mma16816(accz[mt], af[mt], onesb);
                }
            }
            mbar_arrive(mb + 8 * (NBUF + st));
        }

        // publish Z (warp column 0; value replicated across each lane quad)
        if (zwarp && (lane & 3) == 0) {
            const int lr4 = lane >> 2;
            #pragma unroll
            for (int mt = 0; mt < 2; ++mt) {
                zs[m0 + mt * 16 + lr4] = accz[mt][0];
                zs[m0 + mt * 16 + lr4 + 8] = accz[mt][2];
            }
        }
        asm volatile("bar.sync 1, 512;" ::: "memory");   // consumers only

        // epilogue: scale by 1/Z and store
        const int lr4 = lane >> 2;
        const int lc2 = (lane & 3) * 2;
        #pragma unroll
        for (int mt = 0; mt < 2; ++mt) {
            const int r0 = m0 + mt * 16 + lr4;
            const float i0 = 1.0f / zs[r0];
            const float i1 = 1.0f / zs[r0 + 8];
            float* o0 = Out + ((size_t)b * SEQL + s0 + r0) * DIM + n0 + lc2;
            float* o1 = o0 + 8 * DIM;
            #pragma unroll
            for (int nt = 0; nt < 4; ++nt) {
                *(float2*)(o0 + nt * 8) = make_float2(acc[mt][nt][0] * i0, acc[mt][nt][1] * i0);
                *(float2*)(o1 + nt * 8) = make_float2(acc[mt][nt][2] * i1, acc[mt][nt][3] * i1);
            }
        }
    }
}

// ---------------------------------------------------------------------------
// Harness entry
// ---------------------------------------------------------------------------
extern "C" void kernel_launch(void* const* d_in, const int* in_sizes, int n_in,
                              void* d_out, int out_size) {
    const float* X = (const float*)d_in[0];    // [8, 2048, 128] f32
    const float* rot = (const float*)d_in[1];  // [384] f32
    const float* ent = (const float*)d_in[2];  // [128] f32
    float* Out = (float*)d_out;                // [8, 2048, 128] f32

    rowdot_kernel<<<NROWS / 32, 256>>>(X, rot, ent);
    attn_mma_kernel<<<dim3(SEQL / 128, BATCH), 640>>>(Out);
}

// round 12
// speedup vs baseline: 4.2107x; 1.0783x over previous
#include <cuda_runtime.h>
#include <cuda_fp16.h>
#include <cstdint>

#define BATCH 8
#define SEQL 2048
#define DIM 128
#define NROWS (BATCH*SEQL)
#define SCALE 0.08838834764831843f    // 1/sqrt(128)
#define LOG2E 1.4426950408889634f
#define KT 32
#define NCHUNK (SEQL/KT)
#define NBUF 3
#define WS 40     // W smem row stride (halves): 80B -> conflict-free ldmatrix
#define XS 136    // X smem row stride (halves): 272B -> conflict-free ldmatrix
#define WBYTES (128 * WS * 2)          // 10240
#define XBYTES (KT * XS * 2)           // 8704
#define BUFBYTES (WBYTES + XBYTES)     // 18944
#define DYN_SMEM (NBUF * BUFBYTES)     // 56832

typedef unsigned long long ull;

__device__ __align__(16) float g_a2[NROWS];   // a * SCALE * log2(e)
__device__ __align__(16) float g_k[NROWS];
__device__ unsigned g_kmaxu[BATCH];           // order-encoded max(k)   (zero-init ok)
__device__ unsigned g_knegu[BATCH];           // order-encoded max(-k)  (zero-init ok)
__device__ __align__(16) __half g_xh[(size_t)NROWS * DIM];   // X in fp16

// ---------------------------------------------------------------------------
// helpers
// ---------------------------------------------------------------------------
__device__ __forceinline__ uint32_t smem_u32(const void* p) {
    uint32_t a;
    asm("{ .reg .u64 t; cvta.to.shared.u64 t, %1; cvt.u32.u64 %0, t; }" : "=r"(a) : "l"(p));
    return a;
}
__device__ __forceinline__ float ex2f(float x) {
    float r; asm("ex2.approx.f32 %0, %1;" : "=f"(r) : "f"(x)); return r;
}
// packs lo=b, hi=a
__device__ __forceinline__ uint32_t packh2f(float hi, float lo) {
    uint32_t r;
    asm("cvt.rn.f16x2.f32 %0, %1, %2;" : "=r"(r) : "f"(hi), "f"(lo));
    return r;
}
// order-preserving float<->uint encode (monotonic; 0 below all real encodes)
__device__ __forceinline__ unsigned fenc(float x) {
    unsigned b = __float_as_uint(x);
    return (b & 0x80000000u) ? ~b : (b | 0x80000000u);
}
__device__ __forceinline__ float fdec(unsigned u) {
    return __uint_as_float((u & 0x80000000u) ? (u & 0x7FFFFFFFu) : ~u);
}
__device__ __forceinline__ void ldsm4(uint32_t* r, uint32_t addr) {
    asm volatile("ldmatrix.sync.aligned.m8n8.x4.shared.b16 {%0,%1,%2,%3}, [%4];"
                 : "=r"(r[0]), "=r"(r[1]), "=r"(r[2]), "=r"(r[3]) : "r"(addr));
}
__device__ __forceinline__ void ldsm4t(uint32_t* r, uint32_t addr) {
    asm volatile("ldmatrix.sync.aligned.m8n8.x4.trans.shared.b16 {%0,%1,%2,%3}, [%4];"
                 : "=r"(r[0]), "=r"(r[1]), "=r"(r[2]), "=r"(r[3]) : "r"(addr));
}
__device__ __forceinline__ void mma16816(float* d, const uint32_t* a, const uint32_t* b) {
    asm volatile(
        "mma.sync.aligned.m16n8k16.row.col.f32.f16.f16.f32 "
        "{%0,%1,%2,%3}, {%4,%5,%6,%7}, {%8,%9}, {%0,%1,%2,%3};"
        : "+f"(d[0]), "+f"(d[1]), "+f"(d[2]), "+f"(d[3])
        : "r"(a[0]), "r"(a[1]), "r"(a[2]), "r"(a[3]), "r"(b[0]), "r"(b[1]));
}
__device__ __forceinline__ void mbar_init(uint32_t a, uint32_t cnt) {
    asm volatile("mbarrier.init.shared.b64 [%0], %1;" :: "r"(a), "r"(cnt) : "memory");
}
__device__ __forceinline__ void mbar_arrive(uint32_t a) {
    asm volatile("mbarrier.arrive.shared.b64 _, [%0];" :: "r"(a) : "memory");
}
__device__ __forceinline__ void mbar_wait(uint32_t a, uint32_t par) {
    asm volatile(
        "{\n\t.reg .pred P;\n"
        "W%=:\n\t"
        "mbarrier.try_wait.parity.acquire.cta.shared::cta.b64 P, [%0], %1, 0x989680;\n\t"
        "@!P bra W%=;\n\t}"
        :: "r"(a), "r"(par) : "memory");
}

// ---------------------------------------------------------------------------
// Kernel 1: per-row dots + X -> fp16 + fused per-batch k min/max atomics.
// ---------------------------------------------------------------------------
__global__ void __launch_bounds__(256) rowdot_kernel(const float* __restrict__ X,
                                                     const float* __restrict__ rot,
                                                     const float* __restrict__ ent) {
    __shared__ float rs[DIM];
    const int tid = threadIdx.x;
    if (tid < DIM) {
        const float* rp = rot + tid * 3;
        rs[tid] = rp[0] + rp[1] + rp[2];
    }
    __syncthreads();

    const int lane = tid & 31;
    const int wid = tid >> 5;
    const int c8 = lane & 7;
    const int rg = lane >> 3;
    const int row = blockIdx.x * 32 + wid * 4 + rg;

    const float4* Xr = (const float4*)X + (size_t)row * 32;

    float4 x[4];
    #pragma unroll
    for (int j = 0; j < 4; ++j) x[j] = Xr[c8 + 8 * j];

    float da = 0.f, dk = 0.f;
    #pragma unroll
    for (int j = 0; j < 4; ++j) {
        const int c = (c8 + 8 * j) * 4;
        uint2 v;
        v.x = packh2f(x[j].y, x[j].x);
        v.y = packh2f(x[j].w, x[j].z);
        *(uint2*)(g_xh + (size_t)row * DIM + c) = v;

        da += x[j].x * rs[c] + x[j].y * rs[c + 1] + x[j].z * rs[c + 2] + x[j].w * rs[c + 3];
        dk += x[j].x * ent[c] + x[j].y * ent[c + 1] + x[j].z * ent[c + 2] + x[j].w * ent[c + 3];
    }

    da += __shfl_xor_sync(~0u, da, 4); dk += __shfl_xor_sync(~0u, dk, 4);
    da += __shfl_xor_sync(~0u, da, 2); dk += __shfl_xor_sync(~0u, dk, 2);
    da += __shfl_xor_sync(~0u, da, 1); dk += __shfl_xor_sync(~0u, dk, 1);

    if (c8 == 0) {
        g_a2[row] = da * (SCALE * LOG2E);
        g_k[row] = dk;
    }
    float kx = dk, kn = dk;
    kx = fmaxf(kx, __shfl_xor_sync(~0u, kx, 8));  kn = fminf(kn, __shfl_xor_sync(~0u, kn, 8));
    kx = fmaxf(kx, __shfl_xor_sync(~0u, kx, 16)); kn = fminf(kn, __shfl_xor_sync(~0u, kn, 16));
    if (lane == 0) {
        const int bt = row >> 11;
        atomicMax(&g_kmaxu[bt], fenc(kx));
        atomicMax(&g_knegu[bt], fenc(-kn));
    }
}

// ---------------------------------------------------------------------------
// Kernel 2: warp-specialized fp16 mma.sync attention GEMM.
// 640 threads = 16 consumer warps + 4 producer warps.  NBUF=3 ring in
// dynamic smem; producer prefetches next chunk's X into registers so LDG
// latency overlaps MUFU + empty-wait.  No __syncthreads in the main loop.
// ---------------------------------------------------------------------------
__global__ void __launch_bounds__(640, 1) attn_mma_kernel(float* __restrict__ Out) {
    extern __shared__ __align__(16) char dyn[];
    __shared__ float zs[128];
    __shared__ __align__(8) ull s_mbar[2 * NBUF];  // [0..2] full, [3..5] empty

    const int tid = threadIdx.x;
    const int wid = tid >> 5;
    const int lane = tid & 31;
    const int b = blockIdx.y;
    const int s0 = blockIdx.x * 128;
    const uint32_t mb = smem_u32((const void*)&s_mbar[0]);
    const uint32_t dynB = smem_u32(dyn);

    if (tid == 0) {
        #pragma unroll
        for (int s = 0; s < NBUF; ++s) {
            mbar_init(mb + 8 * s, 128);              // full: 128 producer arrivals
            mbar_init(mb + 8 * (NBUF + s), 512);     // empty: 512 consumer arrivals
        }
    }
    __syncthreads();

    if (wid >= 16) {
        // ============================ PRODUCER ============================
        const int ptid = tid - 512;                  // 0..127
        const float a2 = g_a2[b * SEQL + s0 + ptid];
        const float kmx = fdec(g_kmaxu[b]);
        const float kmn = -fdec(g_knegu[b]);
        const float nm2 = -((a2 >= 0.f) ? a2 * kmx : a2 * kmn);
        const float* kb = g_k + b * SEQL;
        const __half* XHb = g_xh + (size_t)b * SEQL * DIM;
        const int xtp = ptid >> 2;                   // 0..31  (X row)
        const int xdp = (ptid & 3) * 32;             // halves offset

        // prefetch chunk 0 X
        uint4 xp[4];
        {
            const uint4* xsrc = (const uint4*)(XHb + (size_t)xtp * DIM + xdp);
            xp[0] = xsrc[0]; xp[1] = xsrc[1]; xp[2] = xsrc[2]; xp[3] = xsrc[3];
        }

        int st = 0, ph = 0;
        for (int c = 0; c < NCHUNK; ++c) {
            if (c >= NBUF) mbar_wait(mb + 8 * (NBUF + st), ph ^ 1);

            // stage prefetched X
            uint4* xdst = (uint4*)(dyn + st * BUFBYTES + WBYTES + (xtp * XS + xdp) * 2);
            xdst[0] = xp[0]; xdst[1] = xp[1]; xdst[2] = xp[2]; xdst[3] = xp[3];

            // issue next chunk's LDGs now (latency hidden under W-gen below)
            if (c + 1 < NCHUNK) {
                const uint4* xsrc = (const uint4*)(XHb + (size_t)((c + 1) * KT + xtp) * DIM + xdp);
                xp[0] = xsrc[0]; xp[1] = xsrc[1]; xp[2] = xsrc[2]; xp[3] = xsrc[3];
            }

            // stage W row ptid: 32 exps -> 4 x uint4
            const float4* kc = (const float4*)(kb + c * KT);
            uint4* wdst = (uint4*)(dyn + st * BUFBYTES + ptid * (WS * 2));
            #pragma unroll
            for (int j = 0; j < 4; ++j) {
                float4 k0 = kc[2 * j], k1 = kc[2 * j + 1];
                float w0 = ex2f(fmaf(a2, k0.x, nm2)), w1 = ex2f(fmaf(a2, k0.y, nm2));
                float w2 = ex2f(fmaf(a2, k0.z, nm2)), w3 = ex2f(fmaf(a2, k0.w, nm2));
                float w4 = ex2f(fmaf(a2, k1.x, nm2)), w5 = ex2f(fmaf(a2, k1.y, nm2));
                float w6 = ex2f(fmaf(a2, k1.z, nm2)), w7 = ex2f(fmaf(a2, k1.w, nm2));
                uint4 q;
                q.x = packh2f(w1, w0); q.y = packh2f(w3, w2);
                q.z = packh2f(w5, w4); q.w = packh2f(w7, w6);
                wdst[j] = q;
            }
            mbar_arrive(mb + 8 * st);
            if (++st == NBUF) { st = 0; ph ^= 1; }
        }
    } else {
        // ============================ CONSUMER ============================
        const int m0 = (wid & 3) * 32;
        const int n0 = (wid >> 2) * 32;
        const bool zwarp = (wid >> 2) == 0;
        const uint32_t onesb[2] = {0x3C003C00u, 0x3C003C00u};

        float acc[2][4][4];
        float accz[2][4];
        #pragma unroll
        for (int i = 0; i < 2; i++) {
            #pragma unroll
            for (int q = 0; q < 4; q++) accz[i][q] = 0.f;
            #pragma unroll
            for (int j = 0; j < 4; j++)
                #pragma unroll
                for (int q = 0; q < 4; q++) acc[i][j][q] = 0.f;
        }

        const int lr = lane & 15, lc = lane >> 4;

        int st = 0, ph = 0;
        for (int c = 0; c < NCHUNK; ++c) {
            mbar_wait(mb + 8 * st, ph);

            const uint32_t wbB = dynB + st * BUFBYTES;
            const uint32_t xbB = wbB + WBYTES;
            #pragma unroll
            for (int kp = 0; kp < 2; ++kp) {
                uint32_t af[2][4];
                #pragma unroll
                for (int mt = 0; mt < 2; ++mt)
                    ldsm4(af[mt], wbB + (uint32_t)(((m0 + mt * 16 + lr) * WS + kp * 16 + lc * 8) * 2));
                uint32_t bf[2][4];
                #pragma unroll
                for (int q = 0; q < 2; ++q)
                    ldsm4t(bf[q], xbB + (uint32_t)(((kp * 16 + lr) * XS + n0 + q * 16 + lc * 8) * 2));
                #pragma unroll
                for (int mt = 0; mt < 2; ++mt) {
                    #pragma unroll
                    for (int nt = 0; nt < 4; ++nt)
                        mma16816(acc[mt][nt], af[mt], &bf[nt >> 1][(nt & 1) * 2]);
                    if (zwarp) mma16816(accz[mt], af[mt], onesb);
                }
            }
            mbar_arrive(mb + 8 * (NBUF + st));
            if (++st == NBUF) { st = 0; ph ^= 1; }
        }

        // publish Z (warp column 0; value replicated across each lane quad)
        if (zwarp && (lane & 3) == 0) {
            const int lr4 = lane >> 2;
            #pragma unroll
            for (int mt = 0; mt < 2; ++mt) {
                zs[m0 + mt * 16 + lr4] = accz[mt][0];
                zs[m0 + mt * 16 + lr4 + 8] = accz[mt][2];
            }
        }
        asm volatile("bar.sync 1, 512;" ::: "memory");   // consumers only

        // epilogue: scale by 1/Z and store
        const int lr4 = lane >> 2;
        const int lc2 = (lane & 3) * 2;
        #pragma unroll
        for (int mt = 0; mt < 2; ++mt) {
            const int r0 = m0 + mt * 16 + lr4;
            const float i0 = 1.0f / zs[r0];
            const float i1 = 1.0f / zs[r0 + 8];
            float* o0 = Out + ((size_t)b * SEQL + s0 + r0) * DIM + n0 + lc2;
            float* o1 = o0 + 8 * DIM;
            #pragma unroll
            for (int nt = 0; nt < 4; ++nt) {
                *(float2*)(o0 + nt * 8) = make_float2(acc[mt][nt][0] * i0, acc[mt][nt][1] * i0);
                *(float2*)(o1 + nt * 8) = make_float2(acc[mt][nt][2] * i1, acc[mt][nt][3] * i1);
            }
        }
    }
}

// ---------------------------------------------------------------------------
// Harness entry
// ---------------------------------------------------------------------------
extern "C" void kernel_launch(void* const* d_in, const int* in_sizes, int n_in,
                              void* d_out, int out_size) {
    const float* X = (const float*)d_in[0];    // [8, 2048, 128] f32
    const float* rot = (const float*)d_in[1];  // [384] f32
    const float* ent = (const float*)d_in[2];  // [128] f32
    float* Out = (float*)d_out;                // [8, 2048, 128] f32

    cudaFuncSetAttribute(attn_mma_kernel,
                         cudaFuncAttributeMaxDynamicSharedMemorySize, DYN_SMEM);

    rowdot_kernel<<<NROWS / 32, 256>>>(X, rot, ent);
    attn_mma_kernel<<<dim3(SEQL / 128, BATCH), 640, DYN_SMEM>>>(Out);
}